// round 10
// baseline (speedup 1.0000x reference)
#include <cuda_runtime.h>
#include <cstdint>
#include <math.h>

// Problem: B=4, T=4096, C=2048, E=64, K=8
#define NTOK   16384
#define CDIM   2048
#define NEXP   64
#define KTOP   8
#define BM     128
#define BK     32
#define NCHUNK (CDIM / BK)   // 64
#define NKTOT  (NTOK * KTOP)
#define NTHR   512

// smem: A [2][BK][APITCH] plain, B [2][BK][BPITCH2] duplicated ({v,v} per expert).
// A region reused as logits [128][65] (33280B <= 33792B).
#define APITCH  132
#define BPITCH2 136              // 128 dup'd floats + 8 pad
#define ABUF    (BK * APITCH)    // 4224 floats
#define BBUF    (BK * BPITCH2)   // 4352 floats
#define AREG    (2 * ABUF)
#define SMEM_DYN ((AREG + 2 * BBUF) * 4)   // 68608 bytes

__device__ float g_counts[NEXP];
__device__ int   g_done = 0;

// --- packed fp32x2 helpers (B300: scalar FFMA is half-rate; f32x2 is full-rate) ---
__device__ __forceinline__ unsigned long long dup2(float x) {
    unsigned long long r;
    asm("mov.b64 %0, {%1, %1};" : "=l"(r) : "f"(x));
    return r;
}
__device__ __forceinline__ void fma2(unsigned long long& d, unsigned long long a, unsigned long long b) {
    asm("fma.rn.f32x2 %0, %1, %2, %0;" : "+l"(d) : "l"(a), "l"(b));
}
__device__ __forceinline__ float2 unpack2(unsigned long long v) {
    float2 f;
    asm("mov.b64 {%0, %1}, %2;" : "=f"(f.x), "=f"(f.y) : "l"(v));
    return f;
}

// XOR 4-block swizzle (A, 4-float blocks): element v at k-row u -> storage position.
__device__ __forceinline__ int swzA(int v, int u) {
    return (((v >> 2) ^ (u >> 2)) << 2) | (v & 3);
}
// dup'd B store: expert e value v at k-row u -> {v,v} (8B), swizzled in 8B units.
__device__ __forceinline__ void stsB(float* Bsn, int e, int u, float v) {
    const int pe = (((e >> 2) ^ (u >> 2)) << 2) | (e & 3);   // position in 8B units
    *(unsigned long long*)(Bsn + u * BPITCH2 + 2 * pe) = dup2(v);
}

// larger value wins; ties -> smaller expert index (matches jax.lax.top_k)
__device__ __forceinline__ unsigned long long sortkey(float v, int e) {
    unsigned u = __float_as_uint(v);
    u = (u & 0x80000000u) ? ~u : (u | 0x80000000u);
    return ((unsigned long long)u << 32) | (unsigned)(63 - e);
}

// Fused: GEMM (x @ W^T) -> logits -> sigmoid/top-8/normalize -> outputs + bincount -> maxvio.
// Grid: 128 blocks (1/SM), 512 threads (4 warps/SMSP), 4 tok x 4 exp per thread.
// Zero-MOV mainloop: B stored pre-duplicated, A plain.
__global__ __launch_bounds__(NTHR, 1) void k_gate(
    const float* __restrict__ X,    // [NTOK, CDIM]
    const int* __restrict__ mask,   // [NTOK] bool as int32
    const float* __restrict__ W,    // [NEXP, CDIM]
    const float* __restrict__ gb,   // [NEXP]
    const float* __restrict__ eb,   // [NEXP]
    float* __restrict__ out,        // [NKTOT idx | NKTOT probs | 1 maxvio]
    int pos)
{
    extern __shared__ float smem[];
    __shared__ float sGb[NEXP], sEb[NEXP], sCnt[NEXP];
    __shared__ int sLast;

    float* As = smem;               // [2][BK][APITCH],  swizzled [k][m]
    float* Bs = smem + AREG;        // [2][BK][BPITCH2], dup'd swizzled [k][n]

    const int tid  = threadIdx.x;
    const int lane = tid & 31;
    const int wid  = tid >> 5;
    const int tx   = (wid & 1) * 8 + (lane & 7);    // experts tx*4 .. +3  (0..15)
    const int ty   = (wid >> 1) * 4 + (lane >> 3);  // tokens  ty*4 .. +3  (0..31)
    const int tok0 = blockIdx.x * BM;

    if (tid < NEXP) { sGb[tid] = gb[tid]; sEb[tid] = eb[tid]; sCnt[tid] = 0.f; }

    // global->smem transpose mapping: A 1024 float4/chunk (2/thr), B 512 (1/thr)
    int ar[2], ac[2];
    const float* Ag[2];
#pragma unroll
    for (int p = 0; p < 2; p++) {
        int idx = tid + p * NTHR;
        ar[p] = idx >> 3; ac[p] = (idx & 7) * 4;
        Ag[p] = X + (size_t)(tok0 + ar[p]) * CDIM + ac[p];
    }
    const int br = tid >> 3, bc = (tid & 7) * 4;
    const float* Bg = W + (size_t)br * CDIM + bc;

    // accumulators: 2 token-pairs (f32x2) x 4 experts
    unsigned long long acc[2][4];
#pragma unroll
    for (int i = 0; i < 2; i++)
#pragma unroll
        for (int j = 0; j < 4; j++) acc[i][j] = 0ull;

    // ---- prologue: chunk 0 -> buffer 0 ----
    {
        float4 a[2], b;
#pragma unroll
        for (int p = 0; p < 2; p++) a[p] = *(const float4*)Ag[p];
        b = *(const float4*)Bg;
#pragma unroll
        for (int p = 0; p < 2; p++)
#pragma unroll
            for (int c = 0; c < 4; c++) {
                const int u = ac[p] + c;
                As[u * APITCH + swzA(ar[p], u)] = ((const float*)&a[p])[c];
            }
#pragma unroll
        for (int c = 0; c < 4; c++)
            stsB(Bs, br, bc + c, ((const float*)&b)[c]);
    }
    __syncthreads();

    for (int t = 0; t < NCHUNK; t++) {
        const int cur = t & 1;
        float4 an[2], bn;
        if (t + 1 < NCHUNK) {
            const int off = (t + 1) * BK;
#pragma unroll
            for (int p = 0; p < 2; p++) an[p] = *(const float4*)(Ag[p] + off);
            bn = *(const float4*)(Bg + off);
        }

        const float* Ab = As + cur * ABUF;
        const float* Bb = Bs + cur * BBUF;
#pragma unroll
        for (int k = 0; k < BK; k++) {
            const int s = k >> 2;
            // 4 tokens as 2 packed f32x2 pairs
            ulonglong2 a01 = *(const ulonglong2*)(Ab + k * APITCH + ((ty ^ s) << 2));
            // 4 experts, pre-duplicated: {e0,e0},{e1,e1},{e2,e2},{e3,e3}
            const float* bp = Bb + k * BPITCH2 + ((tx ^ s) << 3);
            ulonglong2 b01 = *(const ulonglong2*)bp;
            ulonglong2 b23 = *(const ulonglong2*)(bp + 4);
            fma2(acc[0][0], a01.x, b01.x); fma2(acc[0][1], a01.x, b01.y);
            fma2(acc[0][2], a01.x, b23.x); fma2(acc[0][3], a01.x, b23.y);
            fma2(acc[1][0], a01.y, b01.x); fma2(acc[1][1], a01.y, b01.y);
            fma2(acc[1][2], a01.y, b23.x); fma2(acc[1][3], a01.y, b23.y);
        }

        if (t + 1 < NCHUNK) {
            float* Asn = As + (1 - cur) * ABUF;
            float* Bsn = Bs + (1 - cur) * BBUF;
#pragma unroll
            for (int p = 0; p < 2; p++)
#pragma unroll
                for (int c = 0; c < 4; c++) {
                    const int u = ac[p] + c;
                    Asn[u * APITCH + swzA(ar[p], u)] = ((const float*)&an[p])[c];
                }
#pragma unroll
            for (int c = 0; c < 4; c++)
                stsB(Bsn, br, bc + c, ((const float*)&bn)[c]);
            __syncthreads();
        }
    }
    __syncthreads();   // GEMM done; smem free for reuse

    // ---- logits tile Ls[m][n], stride 65, +gate_bias ----
    float* Ls = smem;
#pragma unroll
    for (int i = 0; i < 2; i++)
#pragma unroll
        for (int j = 0; j < 4; j++) {
            float2 v = unpack2(acc[i][j]);       // (tok 2i, tok 2i+1) for expert j
            const int n = tx * 4 + j;
            const float b = sGb[n];
            Ls[(ty * 4 + 2 * i + 0) * 65 + n] = v.x + b;
            Ls[(ty * 4 + 2 * i + 1) * 65 + n] = v.y + b;
        }
    __syncthreads();

    // ---- warp-per-token top-8 of 64 (proven epilogue); 16 warps x 8 tokens ----
    const float eb0 = sEb[lane], eb1 = sEb[lane + 32];
    for (int q = 0; q < 8; q++) {
        const int m = wid * 8 + q;
        const int tok = tok0 + m;
        const float* row = Ls + m * 65;
        const float g0 = row[lane], g1 = row[lane + 32];
        const float s0 = g0 + eb0, s1 = g1 + eb1;
        bool u0 = false, u1 = false;
        float selIdx = 0.f, selProb = 0.f;
        const int mk = mask[tok];

#pragma unroll
        for (int it = 0; it < KTOP; it++) {
            unsigned long long k0 = u0 ? 0ull : sortkey(s0, lane);
            unsigned long long k1 = u1 ? 0ull : sortkey(s1, lane + 32);
            unsigned long long key = k0 > k1 ? k0 : k1;
#pragma unroll
            for (int o = 16; o; o >>= 1) {
                unsigned long long oth = __shfl_xor_sync(0xffffffffu, key, o);
                if (oth > key) key = oth;
            }
            const int e = 63 - (int)(key & 63u);
            if (e == lane)      u0 = true;
            if (e == lane + 32) u1 = true;
            if (lane == it) {
                const float g = row[e];
                selIdx = (float)e;
                selProb = 1.f / (1.f + expf(-g));
                if (mk) atomicAdd(&sCnt[e], 1.f);
            }
        }
        float p = (lane < KTOP) ? selProb : 0.f;
        float sum = p;
#pragma unroll
        for (int o = 16; o; o >>= 1) sum += __shfl_xor_sync(0xffffffffu, sum, o);
        if (lane < KTOP) {
            out[(size_t)tok * KTOP + lane]         = selIdx;
            out[NKTOT + (size_t)tok * KTOP + lane] = selProb / sum;
        }
    }

    __syncthreads();
    if (tid < NEXP) {
        const float c = sCnt[tid];
        if (c != 0.f) atomicAdd(&g_counts[tid], c);
    }

    // ---- last block computes maxvio and resets scratch (deterministic) ----
    if (tid == 0) {
        __threadfence();
        sLast = (atomicAdd(&g_done, 1) == (int)gridDim.x - 1) ? 1 : 0;
    }
    __syncthreads();
    if (sLast && wid == 0) {
        float c0 = g_counts[lane], c1 = g_counts[lane + 32];
        float mx = fmaxf(c0, c1);
        float sm = c0 + c1;
#pragma unroll
        for (int o = 16; o; o >>= 1) {
            mx = fmaxf(mx, __shfl_xor_sync(0xffffffffu, mx, o));
            sm += __shfl_xor_sync(0xffffffffu, sm, o);
        }
        if (lane == 0) {
            const float avg = sm / 64.f;
            out[pos] = (mx - avg) / (avg + 1e-5f);
            g_done = 0;
        }
        g_counts[lane] = 0.f;
        g_counts[lane + 32] = 0.f;
    }
}

extern "C" void kernel_launch(void* const* d_in, const int* in_sizes, int n_in,
                              void* d_out, int out_size) {
    const float* X    = (const float*)d_in[0];
    const int*   mask = (const int*)d_in[1];
    const float* W    = (const float*)d_in[2];
    const float* gb   = (const float*)d_in[3];
    const float* eb   = (const float*)d_in[4];
    float*       out  = (float*)d_out;

    cudaFuncSetAttribute(k_gate, cudaFuncAttributeMaxDynamicSharedMemorySize, SMEM_DYN);
    k_gate<<<NTOK / BM, NTHR, SMEM_DYN>>>(X, mask, W, gb, eb, out, out_size - 1);
}

// round 11
// speedup vs baseline: 2.3436x; 2.3436x over previous
#include <cuda_runtime.h>
#include <cstdint>
#include <math.h>

// Problem: B=4, T=4096, C=2048, E=64, K=8
#define NTOK   16384
#define CDIM   2048
#define NEXP   64
#define KTOP   8
#define BM     128
#define BK     32
#define NCHUNK (CDIM / BK)   // 64
#define NKTOT  (NTOK * KTOP)
#define NTHR   512

// smem: A [2][BK][APITCH], B [2][BK][BPITCH]; reused as logits [128][65]
#define APITCH 132
#define BPITCH 68
#define ABUF   (BK * APITCH)             // 4224 floats
#define BBUF   (BK * BPITCH)             // 2176 floats
#define AREG   (2 * ABUF)
#define SMEM_DYN ((AREG + 2 * BBUF) * 4) // 51200 bytes (>= 128*65*4 logits)

__device__ float g_counts[NEXP];
__device__ int   g_done = 0;

// --- packed fp32x2 helpers (B300: scalar FFMA is half-rate; f32x2 is full-rate) ---
__device__ __forceinline__ unsigned long long dup2(float x) {
    unsigned long long r;
    asm("mov.b64 %0, {%1, %1};" : "=l"(r) : "f"(x));
    return r;
}
__device__ __forceinline__ void fma2(unsigned long long& d, unsigned long long a, unsigned long long b) {
    asm("fma.rn.f32x2 %0, %1, %2, %0;" : "+l"(d) : "l"(a), "l"(b));
}
__device__ __forceinline__ float2 unpack2(unsigned long long v) {
    float2 f;
    asm("mov.b64 {%0, %1}, %2;" : "=f"(f.x), "=f"(f.y) : "l"(v));
    return f;
}

// XOR 4-block swizzle: element v at k-row u -> storage position (conflict-free STS,
// reads stay 16B-vectorizable).
__device__ __forceinline__ int swz(int v, int u) {
    return (((v >> 2) ^ (u >> 2)) << 2) | (v & 3);
}

// larger value wins; ties -> smaller expert index (matches jax.lax.top_k)
__device__ __forceinline__ unsigned long long sortkey(float v, int e) {
    unsigned u = __float_as_uint(v);
    u = (u & 0x80000000u) ? ~u : (u | 0x80000000u);
    return ((unsigned long long)u << 32) | (unsigned)(63 - e);
}

// Fused: GEMM (x @ W^T) -> logits -> sigmoid/top-8/normalize -> outputs + bincount -> maxvio.
// Grid: 128 blocks (1/SM), 512 threads (4 warps/SMSP), 8 tok x 2 exp per thread.
// Only 2 broadcast dups per k-step -> issue demand (15 instr) < FMA budget (16 cyc).
__global__ __launch_bounds__(NTHR, 1) void k_gate(
    const float* __restrict__ X,    // [NTOK, CDIM]
    const int* __restrict__ mask,   // [NTOK] bool as int32
    const float* __restrict__ W,    // [NEXP, CDIM]
    const float* __restrict__ gb,   // [NEXP]
    const float* __restrict__ eb,   // [NEXP]
    float* __restrict__ out,        // [NKTOT idx | NKTOT probs | 1 maxvio]
    int pos)
{
    extern __shared__ float smem[];
    __shared__ float sGb[NEXP], sEb[NEXP], sCnt[NEXP];
    __shared__ int sLast;

    float* As = smem;               // [2][BK][APITCH], swizzled [k][m]
    float* Bs = smem + AREG;        // [2][BK][BPITCH], swizzled [k][n]

    const int tid  = threadIdx.x;
    const int lane = tid & 31;
    const int wid  = tid >> 5;
    // 32 expert-pair groups x 16 token-octet groups; warp covers 8 exp-groups x 4 tok-groups
    const int tx   = (wid & 3) * 8 + (lane & 7);    // expert pair: experts 2*tx, 2*tx+1  (0..31)
    const int ty   = (wid >> 2) * 4 + (lane >> 3);  // tokens ty*8 .. +7                  (0..15)
    const int tok0 = blockIdx.x * BM;

    if (tid < NEXP) { sGb[tid] = gb[tid]; sEb[tid] = eb[tid]; sCnt[tid] = 0.f; }

    // global->smem transpose mapping: A 1024 float4/chunk (2/thr), B 512 (1/thr)
    int ar[2], ac[2];
    const float* Ag[2];
#pragma unroll
    for (int p = 0; p < 2; p++) {
        int idx = tid + p * NTHR;
        ar[p] = idx >> 3; ac[p] = (idx & 7) * 4;
        Ag[p] = X + (size_t)(tok0 + ar[p]) * CDIM + ac[p];
    }
    const int br = tid >> 3, bc = (tid & 7) * 4;
    const float* Bg = W + (size_t)br * CDIM + bc;

    // accumulators: 4 token-pairs (f32x2 over tokens) x 2 experts
    unsigned long long acc[4][2];
#pragma unroll
    for (int i = 0; i < 4; i++) { acc[i][0] = 0ull; acc[i][1] = 0ull; }

    // ---- prologue: chunk 0 -> buffer 0 (swizzled transpose) ----
    {
        float4 a[2], b;
#pragma unroll
        for (int p = 0; p < 2; p++) a[p] = *(const float4*)Ag[p];
        b = *(const float4*)Bg;
#pragma unroll
        for (int p = 0; p < 2; p++)
#pragma unroll
            for (int c = 0; c < 4; c++) {
                const int u = ac[p] + c;
                As[u * APITCH + swz(ar[p], u)] = ((const float*)&a[p])[c];
            }
#pragma unroll
        for (int c = 0; c < 4; c++) {
            const int u = bc + c;
            Bs[u * BPITCH + swz(br, u)] = ((const float*)&b)[c];
        }
    }
    __syncthreads();

    for (int t = 0; t < NCHUNK; t++) {
        const int cur = t & 1;
        float4 an[2], bn;
        if (t + 1 < NCHUNK) {
            const int off = (t + 1) * BK;
#pragma unroll
            for (int p = 0; p < 2; p++) an[p] = *(const float4*)(Ag[p] + off);
            bn = *(const float4*)(Bg + off);
        }

        const float* Ab = As + cur * ABUF;
        const float* Bb = Bs + cur * BBUF;
#pragma unroll
        for (int k = 0; k < BK; k++) {
            const int s = k >> 2;
            // 8 tokens as 4 packed f32x2 pairs (two 16B loads)
            ulonglong2 a01 = *(const ulonglong2*)(Ab + k * APITCH + ((( 2 * ty)      ^ s) << 2));
            ulonglong2 a23 = *(const ulonglong2*)(Ab + k * APITCH + ((( 2 * ty + 1)  ^ s) << 2));
            // expert pair {2tx, 2tx+1}: contiguous inside a 4-float swizzle block
            float2 bp = *(const float2*)(Bb + k * BPITCH + (((tx >> 1) ^ s) << 2) + (tx & 1) * 2);
            unsigned long long b0 = dup2(bp.x), b1 = dup2(bp.y);
            fma2(acc[0][0], a01.x, b0); fma2(acc[0][1], a01.x, b1);
            fma2(acc[1][0], a01.y, b0); fma2(acc[1][1], a01.y, b1);
            fma2(acc[2][0], a23.x, b0); fma2(acc[2][1], a23.x, b1);
            fma2(acc[3][0], a23.y, b0); fma2(acc[3][1], a23.y, b1);
        }

        if (t + 1 < NCHUNK) {
            float* Asn = As + (1 - cur) * ABUF;
            float* Bsn = Bs + (1 - cur) * BBUF;
#pragma unroll
            for (int p = 0; p < 2; p++)
#pragma unroll
                for (int c = 0; c < 4; c++) {
                    const int u = ac[p] + c;
                    Asn[u * APITCH + swz(ar[p], u)] = ((const float*)&an[p])[c];
                }
#pragma unroll
            for (int c = 0; c < 4; c++) {
                const int u = bc + c;
                Bsn[u * BPITCH + swz(br, u)] = ((const float*)&bn)[c];
            }
            __syncthreads();
        }
    }
    __syncthreads();   // GEMM done; smem free for reuse

    // ---- logits tile Ls[m][n], stride 65, +gate_bias ----
    float* Ls = smem;
#pragma unroll
    for (int i = 0; i < 4; i++)
#pragma unroll
        for (int j = 0; j < 2; j++) {
            float2 v = unpack2(acc[i][j]);       // (tok 2i, tok 2i+1) for expert 2tx+j
            const int n = 2 * tx + j;
            const float b = sGb[n];
            Ls[(ty * 8 + 2 * i + 0) * 65 + n] = v.x + b;
            Ls[(ty * 8 + 2 * i + 1) * 65 + n] = v.y + b;
        }
    __syncthreads();

    // ---- warp-per-token top-8 of 64 (proven epilogue); 16 warps x 8 tokens ----
    const float eb0 = sEb[lane], eb1 = sEb[lane + 32];
    for (int q = 0; q < 8; q++) {
        const int m = wid * 8 + q;
        const int tok = tok0 + m;
        const float* row = Ls + m * 65;
        const float g0 = row[lane], g1 = row[lane + 32];
        const float s0 = g0 + eb0, s1 = g1 + eb1;
        bool u0 = false, u1 = false;
        float selIdx = 0.f, selProb = 0.f;
        const int mk = mask[tok];

#pragma unroll
        for (int it = 0; it < KTOP; it++) {
            unsigned long long k0 = u0 ? 0ull : sortkey(s0, lane);
            unsigned long long k1 = u1 ? 0ull : sortkey(s1, lane + 32);
            unsigned long long key = k0 > k1 ? k0 : k1;
#pragma unroll
            for (int o = 16; o; o >>= 1) {
                unsigned long long oth = __shfl_xor_sync(0xffffffffu, key, o);
                if (oth > key) key = oth;
            }
            const int e = 63 - (int)(key & 63u);
            if (e == lane)      u0 = true;
            if (e == lane + 32) u1 = true;
            if (lane == it) {
                const float g = row[e];
                selIdx = (float)e;
                selProb = 1.f / (1.f + expf(-g));
                if (mk) atomicAdd(&sCnt[e], 1.f);
            }
        }
        float p = (lane < KTOP) ? selProb : 0.f;
        float sum = p;
#pragma unroll
        for (int o = 16; o; o >>= 1) sum += __shfl_xor_sync(0xffffffffu, sum, o);
        if (lane < KTOP) {
            out[(size_t)tok * KTOP + lane]         = selIdx;
            out[NKTOT + (size_t)tok * KTOP + lane] = selProb / sum;
        }
    }

    __syncthreads();
    if (tid < NEXP) {
        const float c = sCnt[tid];
        if (c != 0.f) atomicAdd(&g_counts[tid], c);
    }

    // ---- last block computes maxvio and resets scratch (deterministic) ----
    if (tid == 0) {
        __threadfence();
        sLast = (atomicAdd(&g_done, 1) == (int)gridDim.x - 1) ? 1 : 0;
    }
    __syncthreads();
    if (sLast && wid == 0) {
        float c0 = g_counts[lane], c1 = g_counts[lane + 32];
        float mx = fmaxf(c0, c1);
        float sm = c0 + c1;
#pragma unroll
        for (int o = 16; o; o >>= 1) {
            mx = fmaxf(mx, __shfl_xor_sync(0xffffffffu, mx, o));
            sm += __shfl_xor_sync(0xffffffffu, sm, o);
        }
        if (lane == 0) {
            const float avg = sm / 64.f;
            out[pos] = (mx - avg) / (avg + 1e-5f);
            g_done = 0;
        }
        g_counts[lane] = 0.f;
        g_counts[lane + 32] = 0.f;
    }
}

extern "C" void kernel_launch(void* const* d_in, const int* in_sizes, int n_in,
                              void* d_out, int out_size) {
    const float* X    = (const float*)d_in[0];
    const int*   mask = (const int*)d_in[1];
    const float* W    = (const float*)d_in[2];
    const float* gb   = (const float*)d_in[3];
    const float* eb   = (const float*)d_in[4];
    float*       out  = (float*)d_out;

    cudaFuncSetAttribute(k_gate, cudaFuncAttributeMaxDynamicSharedMemorySize, SMEM_DYN);
    k_gate<<<NTOK / BM, NTHR, SMEM_DYN>>>(X, mask, W, gb, eb, out, out_size - 1);
}